// round 5
// baseline (speedup 1.0000x reference)
#include <cuda_runtime.h>
#include <math.h>
#include <stdint.h>

#define HW 4096
#define LT 12
#define BATCH 16

// State buffers (allocation-free scratch). h needs ping-pong (spatial halo reads),
// c is updated by exactly the thread that owns that (b,hid,pixel) -> in-place OK.
__device__ float g_h0[2][(size_t)BATCH * 128 * HW];   // 2 x 32 MB
__device__ float g_c0[(size_t)BATCH * 128 * HW];      // 32 MB
__device__ float g_h1[2][(size_t)BATCH * 12 * HW];    // 2 x 3 MB
__device__ float g_c1[(size_t)BATCH * 12 * HW];       // 3 MB

__global__ void fill_zero(float* __restrict__ p, int n) {
    int i = blockIdx.x * blockDim.x + threadIdx.x;
    int stride = gridDim.x * blockDim.x;
    for (; i < n; i += stride) p[i] = 0.0f;
}

__device__ __forceinline__ float fast_sigmoid(float x) {
    return 1.0f / (1.0f + __expf(-x));
}
__device__ __forceinline__ float fast_tanh_acc(float x) {
    float e = __expf(2.0f * x);
    return 1.0f - 2.0f / (e + 1.0f);
}

// ---- packed f32x2 helpers (Blackwell FFMA2 path, PTX-only) ----
__device__ __forceinline__ uint64_t pack2(float lo, float hi) {
    uint64_t r;
    asm("mov.b64 %0, {%1, %2};" : "=l"(r) : "r"(__float_as_uint(lo)), "r"(__float_as_uint(hi)));
    return r;
}
__device__ __forceinline__ void unpack2(uint64_t v, float& lo, float& hi) {
    uint32_t l, h;
    asm("mov.b64 {%0, %1}, %2;" : "=r"(l), "=r"(h) : "l"(v));
    lo = __uint_as_float(l);
    hi = __uint_as_float(h);
}
__device__ __forceinline__ void ffma2(uint64_t& acc, uint64_t a, uint64_t b) {
    asm("fma.rn.f32x2 %0, %1, %2, %0;" : "+l"(acc) : "l"(a), "l"(b));
}

// Fused ConvLSTM step: z = conv3x3(cat(in0, h_prev)) + b; gate math; update c,h.
// Block: 16x16 spatial tile x HB hidden channels x 4 gates, one batch image.
// Thread: 1 hid x 4 gates x 4 pixel-PAIRS = 16 f32x2 accumulators (FFMA2).
// HB == NHCG (one hid channel per warp-group lane index hg).
template <int CIN, int C0, int HID, int HB, int NHCG, int MINB>
__global__ void __launch_bounds__(NHCG * 32, MINB)
convlstm_step(const float* __restrict__ in0, int in0_bstride,
              const float* __restrict__ in1,   // h_prev, C1 = CIN-C0 channels
              const float* __restrict__ W,     // (4*HID, CIN, 3, 3)
              const float* __restrict__ bias,  // (4*HID)
              float* __restrict__ c_state,     // (B, HID, 64, 64) in/out
              float* __restrict__ h_out)       // (B, HID, 64, 64)
{
    constexpr int THREADS = NHCG * 32;
    constexpr int ICB = 8;
    constexpr int NCHUNK = (CIN + ICB - 1) / ICB;
    constexpr int C1 = CIN - C0;

    __shared__ __align__(16) float si[ICB * 18 * 20];       // input tile + halo, row pad 20
    __shared__ __align__(16) float swd[ICB * 9 * HB * 8];   // [ci][tap][hc][gate][dup] duplicated

    const int tid  = threadIdx.x;
    const int pg   = tid & 31;     // pixel group (32): 16 rows x 2 col-octs
    const int hg   = tid >> 5;     // hid channel within block (0..HB-1)
    const int row  = pg >> 1;
    const int colg = pg & 1;
    const int ty0  = (blockIdx.x >> 2) << 4;
    const int tx0  = (blockIdx.x & 3) << 4;
    const int hid0 = blockIdx.y * HB;
    const int b    = blockIdx.z;

    const float* in0b = in0 + (size_t)b * in0_bstride;
    const float* in1b = in1 + (size_t)b * C1 * HW;

    uint64_t acc2[4][4];   // [gate][pixel-pair]
#pragma unroll
    for (int g = 0; g < 4; ++g)
#pragma unroll
        for (int jp = 0; jp < 4; ++jp) acc2[g][jp] = 0ull;

    for (int ch = 0; ch < NCHUNK; ++ch) {
        const int ic0 = ch * ICB;
        // ---- load input tile (8 ch x 18x18 with halo, zero-pad edges/overrun)
        for (int idx = tid; idx < ICB * 18 * 18; idx += THREADS) {
            int ci  = idx / 324;
            int rem = idx - ci * 324;
            int r   = rem / 18;
            int c   = rem - r * 18;
            int cg  = ic0 + ci;
            int gy  = ty0 - 1 + r;
            int gx  = tx0 - 1 + c;
            float v = 0.0f;
            if (cg < CIN && (unsigned)gy < 64u && (unsigned)gx < 64u) {
                v = (cg < C0) ? __ldg(&in0b[(size_t)cg * HW + gy * 64 + gx])
                              : __ldg(&in1b[(size_t)(cg - C0) * HW + gy * 64 + gx]);
            }
            si[ci * 360 + r * 20 + c] = v;
        }
        // ---- load weight slab DUPLICATED: swd[(((ci*9+tap)*HB + hc)*4 + g)*2 + dup]
        for (int idx = tid; idx < ICB * 9 * HB * 8; idx += THREADS) {
            int g   = (idx >> 1) & 3;
            int t2  = idx >> 3;
            int hc  = t2 % HB;
            int t3  = t2 / HB;
            int tap = t3 % 9;
            int ci  = t3 / 9;
            int cg  = ic0 + ci;
            float wv = 0.0f;
            if (cg < CIN) {
                int oc = g * HID + hid0 + hc;
                wv = __ldg(&W[((size_t)oc * CIN + cg) * 9 + tap]);
            }
            swd[idx] = wv;
        }
        __syncthreads();

        // ---- compute: 144 FFMA2 / thread / chunk
#pragma unroll
        for (int ci = 0; ci < ICB; ++ci) {
            const float* sib = &si[ci * 360 + row * 20 + colg * 8];
#pragma unroll
            for (int dy = 0; dy < 3; ++dy) {
                float r0[10];
                const float4 a0 = *(const float4*)(sib + dy * 20);
                const float4 a1 = *(const float4*)(sib + dy * 20 + 4);
                const float2 a2 = *(const float2*)(sib + dy * 20 + 8);
                r0[0] = a0.x; r0[1] = a0.y; r0[2] = a0.z; r0[3] = a0.w;
                r0[4] = a1.x; r0[5] = a1.y; r0[6] = a1.z; r0[7] = a1.w;
                r0[8] = a2.x; r0[9] = a2.y;
                // even pairs {r2k, r2k+1}, odd pairs {r2k+1, r2k+2}
                uint64_t pe[5], po[4];
#pragma unroll
                for (int k = 0; k < 5; ++k) pe[k] = pack2(r0[2 * k], r0[2 * k + 1]);
#pragma unroll
                for (int k = 0; k < 4; ++k) po[k] = pack2(r0[2 * k + 1], r0[2 * k + 2]);
#pragma unroll
                for (int dx = 0; dx < 3; ++dx) {
                    const int tap = dy * 3 + dx;
                    // duplicated packed weights: broadcast LDS, already f32x2-shaped
                    const float* wb = &swd[((ci * 9 + tap) * HB + hg) * 8];
                    const ulonglong2 wA = *(const ulonglong2*)(wb);       // {g0g0, g1g1}
                    const ulonglong2 wB = *(const ulonglong2*)(wb + 4);   // {g2g2, g3g3}
#pragma unroll
                    for (int jp = 0; jp < 4; ++jp) {
                        const uint64_t v = (dx == 0) ? pe[jp] : (dx == 1) ? po[jp] : pe[jp + 1];
                        ffma2(acc2[0][jp], wA.x, v);
                        ffma2(acc2[1][jp], wA.y, v);
                        ffma2(acc2[2][jp], wB.x, v);
                        ffma2(acc2[3][jp], wB.y, v);
                    }
                }
            }
        }
        __syncthreads();
    }

    // ---- epilogue: bias + gates + state update
    {
        const int hch = hid0 + hg;
        const float bi = bias[0 * HID + hch];
        const float bf = bias[1 * HID + hch];
        const float bo = bias[2 * HID + hch];
        const float bg = bias[3 * HID + hch];
        const int gy  = ty0 + row;
        const int gxb = tx0 + colg * 8;
        const size_t base = ((size_t)b * HID + hch) * HW + gy * 64 + gxb;
#pragma unroll
        for (int jp = 0; jp < 4; ++jp) {
            float zi0, zi1, zf0, zf1, zo0, zo1, zg0, zg1;
            unpack2(acc2[0][jp], zi0, zi1);
            unpack2(acc2[1][jp], zf0, zf1);
            unpack2(acc2[2][jp], zo0, zo1);
            unpack2(acc2[3][jp], zg0, zg1);
#pragma unroll
            for (int s = 0; s < 2; ++s) {
                const int j = jp * 2 + s;
                const float zi = (s ? zi1 : zi0) + bi;
                const float zf = (s ? zf1 : zf0) + bf;
                const float zo = (s ? zo1 : zo0) + bo;
                const float zg = (s ? zg1 : zg0) + bg;
                const float cp = c_state[base + j];
                const float cn = fast_sigmoid(zf) * cp + fast_sigmoid(zi) * fast_tanh_acc(zg);
                const float hn = fast_sigmoid(zo) * fast_tanh_acc(cn);
                c_state[base + j] = cn;
                h_out[base + j]   = hn;
            }
        }
    }
}

extern "C" void kernel_launch(void* const* d_in, const int* in_sizes, int n_in,
                              void* d_out, int out_size) {
    const float* hist = (const float*)d_in[0];
    const float* W0   = (const float*)d_in[2];
    const float* b0   = (const float*)d_in[3];
    const float* W1   = (const float*)d_in[4];
    const float* b1   = (const float*)d_in[5];
    float* out = (float*)d_out;

    float *h0p, *c0p, *h1p, *c1p;
    cudaGetSymbolAddress((void**)&h0p, g_h0);
    cudaGetSymbolAddress((void**)&c0p, g_c0);
    cudaGetSymbolAddress((void**)&h1p, g_h1);
    cudaGetSymbolAddress((void**)&c1p, g_c1);

    const size_t n_s0 = (size_t)BATCH * 128 * HW;   // one h0 buffer
    const size_t n_s1 = (size_t)BATCH * 12 * HW;    // one h1 buffer

    // Reset recurrent state every call (graph replays must be deterministic).
    fill_zero<<<1024, 256>>>(h0p, (int)n_s0);   // g_h0[0]
    fill_zero<<<1024, 256>>>(c0p, (int)n_s0);
    fill_zero<<<64,   256>>>(h1p, (int)n_s1);   // g_h1[0]
    fill_zero<<<64,   256>>>(c1p, (int)n_s1);

    dim3 grid0(16, 16, BATCH), blk0(256);  // 128 hid / 8 per block
    dim3 grid1(16, 1, BATCH), blk1(384);   // 12 hid, one per warp

    for (int t = 0; t < LT; ++t) {
        const float* h0_prev = h0p + (size_t)(t & 1) * n_s0;
        float*       h0_next = h0p + (size_t)((t + 1) & 1) * n_s0;
        const float* h1_prev = h1p + (size_t)(t & 1) * n_s1;
        float*       h1_next = (t == LT - 1) ? out : (h1p + (size_t)((t + 1) & 1) * n_s1);

        // Layer 0: cat(x_t [1ch], h0 [128ch]) -> 512 gate channels
        convlstm_step<129, 1, 128, 8, 8, 2><<<grid0, blk0>>>(
            hist + t * HW, LT * HW, h0_prev, W0, b0, c0p, h0_next);
        // Layer 1: cat(h0_t [128ch], h1 [12ch]) -> 48 gate channels
        convlstm_step<140, 128, 12, 12, 12, 1><<<grid1, blk1>>>(
            h0_next, 128 * HW, h1_prev, W1, b1, c1p, h1_next);
    }
}

// round 8
// speedup vs baseline: 3.2582x; 3.2582x over previous
#include <cuda_runtime.h>
#include <cuda_bf16.h>
#include <stdint.h>
#include <math.h>

#define PADW 66
#define CH   144
#define NB   16
#define LT   12

static constexpr size_t PLANE = (size_t)NB * PADW * PADW * CH;   // bf16 elems per split plane

// ---- persistent scratch ----
__device__ __nv_bfloat16 g_act0[2][2 * PLANE];     // L0 input ping-pong: [hi|lo]
__device__ __nv_bfloat16 g_act1[2][2 * PLANE];     // L1 input ping-pong
__device__ float g_c0[(size_t)NB * 4096 * 128];
__device__ float g_c1[(size_t)NB * 4096 * 12];
__device__ uint32_t g_fb0[9 * 8 * 9 * 2 * 8 * 32 * 2];   // [kc][ntile][tap][bsel][nsub][lane][reg]
__device__ uint32_t g_fb1[9 * 1 * 9 * 2 * 8 * 32 * 2];

__global__ void fill16(uint4* __restrict__ p, size_t n) {
    size_t i = (size_t)blockIdx.x * blockDim.x + threadIdx.x;
    size_t st = (size_t)gridDim.x * blockDim.x;
    uint4 z = make_uint4(0, 0, 0, 0);
    for (; i < n; i += st) p[i] = z;
}

__device__ __forceinline__ float fsig(float x) { return 1.0f / (1.0f + __expf(-x)); }
__device__ __forceinline__ float ftanh(float x) {
    float e = __expf(2.0f * x);
    return 1.0f - 2.0f / (e + 1.0f);
}

// Build per-lane B fragments, gate-interleaved (n' = 4*hid + gate), hi/lo split.
__global__ void prep_w(const float* __restrict__ W, uint32_t* __restrict__ dst,
                       int HIDT, int NTILES, int CIN, int mode0, int total) {
    int idx = blockIdx.x * blockDim.x + threadIdx.x;
    if (idx >= total) return;
    int r    = idx & 1;
    int lane = (idx >> 1) & 31;
    int nsub = (idx >> 6) & 7;
    int bsel = (idx >> 9) & 1;
    int rest = idx >> 10;
    int tap  = rest % 9;  rest /= 9;
    int nt   = rest % NTILES;
    int kc   = rest / NTILES;
    int n    = ((nt * 8 + nsub) << 3) + (lane >> 2);
    int hid  = n >> 2, gate = n & 3;
    int ch0  = kc * 16 + (lane & 3) * 2 + r * 8;
    uint32_t out = 0;
#pragma unroll
    for (int s = 0; s < 2; ++s) {
        int ch = ch0 + s;
        int cin = mode0 ? (ch == 128 ? 0 : (ch < 128 ? ch + 1 : -1))
                        : (ch < CIN ? ch : -1);
        float w = 0.f;
        if (cin >= 0 && hid < HIDT)
            w = W[((size_t)(gate * HIDT + hid) * CIN + cin) * 9 + tap];
        __nv_bfloat16 hi = __float2bfloat16(w);
        __nv_bfloat16 v = bsel ? __float2bfloat16(w - __bfloat162float(hi)) : hi;
        out |= (uint32_t)__bfloat16_as_ushort(v) << (s * 16);
    }
    dst[idx] = out;
}

// Inject x_t at channel 128 (hi/lo) of act0[t&1].
__global__ void inject_x(const float* __restrict__ hist, int t, __nv_bfloat16* __restrict__ act) {
    int idx = blockIdx.x * blockDim.x + threadIdx.x;
    if (idx >= NB * 4096) return;
    int b = idx >> 12, px = idx & 4095;
    float v = hist[((size_t)b * LT + t) * 4096 + px];
    size_t e = (((size_t)b * PADW + (px >> 6) + 1) * PADW + ((px & 63) + 1)) * CH + 128;
    __nv_bfloat16 hi = __float2bfloat16(v);
    act[e] = hi;
    act[PLANE + e] = __float2bfloat16(v - __bfloat162float(hi));
}

// ==================== fused ConvLSTM step: implicit GEMM on mma.sync bf16 ====================
// CTA: M=128 px (2 image rows), N=64 gate-interleaved oc'. 8 warps = 4(M) x 2(N), warp 32x32.
// K loop: pass(A hi/lo) x 9 k-chunks x 9 taps x (B hi[,lo]).
__global__ void __launch_bounds__(256)
step_mma(const __nv_bfloat16* __restrict__ act,      // hi plane; lo = act + PLANE
         const uint32_t* __restrict__ fragB, int ntiles,
         const float* __restrict__ bias, int HIDT,
         float* __restrict__ cstate,
         __nv_bfloat16* hdst_a, __nv_bfloat16* hdst_b, int ch_off,
         float* out_final) {
    extern __shared__ unsigned char smem[];
    __nv_bfloat16* sA = (__nv_bfloat16*)smem;                 // 264 rows x 48B (24 elems)
    uint32_t* sB = (uint32_t*)(smem + 12800);                 // 9216 u32 = 36864B
    const uint32_t sAsh = (uint32_t)__cvta_generic_to_shared(sA);

    const int tid = threadIdx.x, lane = tid & 31, warp = tid >> 5;
    const int warpM = warp & 3, warpN = warp >> 2;
    const int R2 = blockIdx.x * 2;           // image-row base (also padded slab row base)
    const int b  = blockIdx.y;
    const int zt = blockIdx.z;
    const int nro = zt * 64;

    float acc[2][4][4];
#pragma unroll
    for (int m = 0; m < 2; ++m)
#pragma unroll
        for (int i = 0; i < 4; ++i)
#pragma unroll
            for (int k = 0; k < 4; ++k) acc[m][i][k] = 0.f;

    const size_t actbase = ((size_t)b * PADW + R2) * PADW * CH;

    for (int pass = 0; pass < 2; ++pass) {
        const __nv_bfloat16* pl = act + (pass ? PLANE : 0);
        const int nb = pass ? 1 : 2;
        for (int kc = 0; kc < 9; ++kc) {
            __syncthreads();
            // A slab: 264 rows (4 padded rows x 66 px), 16 ch each, row stride 48B
            for (int i = tid; i < 264 * 2; i += 256) {
                int rowid = i >> 1, half = i & 1;
                uint4 v = *(const uint4*)(pl + actbase + (size_t)rowid * CH + kc * 16 + half * 8);
                *(uint4*)(sA + rowid * 24 + half * 8) = v;
            }
            // B block for this (kc, ztile): [tap][bsel][nsub][lane][reg]
            {
                const uint4* src = (const uint4*)fragB + (size_t)(kc * ntiles + zt) * 2304;
                uint4* dst = (uint4*)sB;
                for (int i = tid; i < 2304; i += 256) dst[i] = src[i];
            }
            __syncthreads();
#pragma unroll
            for (int tap = 0; tap < 9; ++tap) {
                const int ky = tap / 3, kx = tap % 3;
                uint32_t a[2][4];
#pragma unroll
                for (int msub = 0; msub < 2; ++msub) {
                    int m = warpM * 32 + msub * 16 + (lane & 15);
                    int srow = ((m >> 6) + ky) * 66 + (m & 63) + kx;
                    uint32_t ad = sAsh + srow * 48 + (lane >> 4) * 16;
                    asm volatile("ldmatrix.sync.aligned.m8n8.x4.shared.b16 {%0,%1,%2,%3}, [%4];"
                        : "=r"(a[msub][0]), "=r"(a[msub][1]), "=r"(a[msub][2]), "=r"(a[msub][3])
                        : "r"(ad));
                }
                for (int bsel = 0; bsel < nb; ++bsel) {
#pragma unroll
                    for (int i = 0; i < 4; ++i) {
                        const uint32_t* bp = sB + ((((tap * 2 + bsel) * 8) + warpN * 4 + i) * 32 + lane) * 2;
                        uint32_t b0 = bp[0], b1 = bp[1];
#pragma unroll
                        for (int msub = 0; msub < 2; ++msub) {
                            asm volatile(
                                "mma.sync.aligned.m16n8k16.row.col.f32.bf16.bf16.f32 "
                                "{%0,%1,%2,%3}, {%4,%5,%6,%7}, {%8,%9}, {%0,%1,%2,%3};"
                                : "+f"(acc[msub][i][0]), "+f"(acc[msub][i][1]),
                                  "+f"(acc[msub][i][2]), "+f"(acc[msub][i][3])
                                : "r"(a[msub][0]), "r"(a[msub][1]), "r"(a[msub][2]), "r"(a[msub][3]),
                                  "r"(b0), "r"(b1));
                        }
                    }
                }
            }
        }
    }

    // ---- epilogue: gather 4 gates per (px,hid) via shfl, LSTM update ----
    const int q = lane & 3;
    const bool evenq = !(q & 1);
#pragma unroll
    for (int msub = 0; msub < 2; ++msub) {
#pragma unroll
        for (int i = 0; i < 4; ++i) {
            float d0 = acc[msub][i][0], d1 = acc[msub][i][1];
            float d2 = acc[msub][i][2], d3 = acc[msub][i][3];
            float s0 = evenq ? d2 : d0;
            float s1 = evenq ? d3 : d1;
            float t0 = __shfl_xor_sync(0xffffffffu, s0, 1);
            float t1 = __shfl_xor_sync(0xffffffffu, s1, 1);
            float zi, zf, zo, zg;
            int pr;
            if (evenq) { zi = d0; zf = d1; zo = t0; zg = t1; pr = lane >> 2; }
            else       { zi = t0; zf = t1; zo = d2; zg = d3; pr = (lane >> 2) + 8; }
            const int m = warpM * 32 + msub * 16 + pr;
            const int hid = (nro >> 2) + warpN * 8 + i * 2 + (q >> 1);
            if (hid < HIDT) {
                zi += bias[hid];
                zf += bias[HIDT + hid];
                zo += bias[2 * HIDT + hid];
                zg += bias[3 * HIDT + hid];
                const int r_im = m >> 6, x = m & 63;
                const size_t cidx = ((size_t)b * 4096 + (R2 + r_im) * 64 + x) * HIDT + hid;
                float cp = cstate[cidx];
                float cn = fsig(zf) * cp + fsig(zi) * ftanh(zg);
                float hn = fsig(zo) * ftanh(cn);
                cstate[cidx] = cn;
                __nv_bfloat16 hi = __float2bfloat16(hn);
                __nv_bfloat16 lo = __float2bfloat16(hn - __bfloat162float(hi));
                const size_t e = (((size_t)b * PADW + R2 + r_im + 1) * PADW + x + 1) * CH + ch_off + hid;
                if (hdst_a) { hdst_a[e] = hi; hdst_a[PLANE + e] = lo; }
                if (hdst_b) { hdst_b[e] = hi; hdst_b[PLANE + e] = lo; }
                if (out_final)
                    out_final[((size_t)b * HIDT + hid) * 4096 + (R2 + r_im) * 64 + x] = hn;
            }
        }
    }
}

// ==================== host ====================
extern "C" void kernel_launch(void* const* d_in, const int* in_sizes, int n_in,
                              void* d_out, int out_size) {
    const float* hist = (const float*)d_in[0];
    const float* W0   = (const float*)d_in[2];
    const float* b0   = (const float*)d_in[3];
    const float* W1   = (const float*)d_in[4];
    const float* b1   = (const float*)d_in[5];
    float* out = (float*)d_out;

    __nv_bfloat16 *a0p, *a1p;
    float *c0p, *c1p;
    uint32_t *fb0, *fb1;
    cudaGetSymbolAddress((void**)&a0p, g_act0);
    cudaGetSymbolAddress((void**)&a1p, g_act1);
    cudaGetSymbolAddress((void**)&c0p, g_c0);
    cudaGetSymbolAddress((void**)&c1p, g_c1);
    cudaGetSymbolAddress((void**)&fb0, g_fb0);
    cudaGetSymbolAddress((void**)&fb1, g_fb1);

    const int SMEM = 12800 + 36864;   // 49664
    cudaFuncSetAttribute(step_mma, cudaFuncAttributeMaxDynamicSharedMemorySize, SMEM);

    // deterministic replay: zero state + activations
    fill16<<<2048, 256>>>((uint4*)a0p, 4 * PLANE / 8);
    fill16<<<2048, 256>>>((uint4*)a1p, 4 * PLANE / 8);
    fill16<<<2048, 256>>>((uint4*)c0p, (size_t)NB * 4096 * 128 / 4);
    fill16<<<512,  256>>>((uint4*)c1p, (size_t)NB * 4096 * 12 / 4);

    const int tot0 = 9 * 8 * 9 * 2 * 8 * 32 * 2;
    const int tot1 = 9 * 1 * 9 * 2 * 8 * 32 * 2;
    prep_w<<<(tot0 + 255) / 256, 256>>>(W0, fb0, 128, 8, 129, 1, tot0);
    prep_w<<<(tot1 + 255) / 256, 256>>>(W1, fb1, 12, 1, 140, 0, tot1);

    const size_t BUF = 2 * PLANE;
    for (int t = 0; t < LT; ++t) {
        __nv_bfloat16* act0_t = a0p + (size_t)(t & 1) * BUF;
        __nv_bfloat16* act0_n = a0p + (size_t)((t + 1) & 1) * BUF;
        __nv_bfloat16* act1_t = a1p + (size_t)(t & 1) * BUF;
        __nv_bfloat16* act1_n = a1p + (size_t)((t + 1) & 1) * BUF;

        inject_x<<<256, 256>>>(hist, t, act0_t);
        // L0: reads act0[t]; writes h0 -> act0[t+1] ch0..127 and act1[t] ch0..127
        step_mma<<<dim3(32, 16, 8), 256, SMEM>>>(
            act0_t, fb0, 8, b0, 128, c0p, act0_n, act1_t, 0, nullptr);
        // L1: reads act1[t]; writes h1 -> act1[t+1] ch128..139; last step -> out
        step_mma<<<dim3(32, 16, 1), 256, SMEM>>>(
            act1_t, fb1, 1, b1, 12, c1p,
            (t < LT - 1) ? act1_n : nullptr, nullptr, 128,
            (t == LT - 1) ? out : nullptr);
    }
}

// round 9
// speedup vs baseline: 4.0282x; 1.2363x over previous
#include <cuda_runtime.h>
#include <cuda_bf16.h>
#include <stdint.h>
#include <math.h>

#define PADW 66
#define CH   144
#define NB   16
#define LT   12

static constexpr size_t PLANE = (size_t)NB * PADW * PADW * CH;   // bf16 elems per split plane

// ---- persistent scratch ----
__device__ __nv_bfloat16 g_act0[2][2 * PLANE];     // L0 input ping-pong: [hi|lo]
__device__ __nv_bfloat16 g_act1[2][2 * PLANE];     // L1 input ping-pong
__device__ float g_c0[(size_t)NB * 4096 * 128];
__device__ float g_c1[(size_t)NB * 4096 * 12];
__device__ uint32_t g_fb0[9 * 8 * 9 * 2 * 8 * 32 * 2];   // [kc][ntile][tap][bsel][nsub][lane][reg]
__device__ uint32_t g_fb1[9 * 1 * 9 * 2 * 8 * 32 * 2];

__global__ void fill16(uint4* __restrict__ p, size_t n) {
    size_t i = (size_t)blockIdx.x * blockDim.x + threadIdx.x;
    size_t st = (size_t)gridDim.x * blockDim.x;
    uint4 z = make_uint4(0, 0, 0, 0);
    for (; i < n; i += st) p[i] = z;
}

__device__ __forceinline__ float fsig(float x) { return 1.0f / (1.0f + __expf(-x)); }
__device__ __forceinline__ float ftanh(float x) {
    float e = __expf(2.0f * x);
    return 1.0f - 2.0f / (e + 1.0f);
}

__device__ __forceinline__ void cpa16(uint32_t dst, const void* src) {
    asm volatile("cp.async.cg.shared.global [%0], [%1], 16;" :: "r"(dst), "l"(src));
}
__device__ __forceinline__ void cpa_commit_wait() {
    asm volatile("cp.async.commit_group;" ::: "memory");
    asm volatile("cp.async.wait_group 0;" ::: "memory");
}

// Build per-lane B fragments, gate-interleaved (n' = 4*hid + gate), hi/lo split.
__global__ void prep_w(const float* __restrict__ W, uint32_t* __restrict__ dst,
                       int HIDT, int NTILES, int CIN, int mode0, int total) {
    int idx = blockIdx.x * blockDim.x + threadIdx.x;
    if (idx >= total) return;
    int r    = idx & 1;
    int lane = (idx >> 1) & 31;
    int nsub = (idx >> 6) & 7;
    int bsel = (idx >> 9) & 1;
    int rest = idx >> 10;
    int tap  = rest % 9;  rest /= 9;
    int nt   = rest % NTILES;
    int kc   = rest / NTILES;
    int n    = ((nt * 8 + nsub) << 3) + (lane >> 2);
    int hid  = n >> 2, gate = n & 3;
    int ch0  = kc * 16 + (lane & 3) * 2 + r * 8;
    uint32_t out = 0;
#pragma unroll
    for (int s = 0; s < 2; ++s) {
        int ch = ch0 + s;
        int cin = mode0 ? (ch == 128 ? 0 : (ch < 128 ? ch + 1 : -1))
                        : (ch < CIN ? ch : -1);
        float w = 0.f;
        if (cin >= 0 && hid < HIDT)
            w = W[((size_t)(gate * HIDT + hid) * CIN + cin) * 9 + tap];
        __nv_bfloat16 hi = __float2bfloat16(w);
        __nv_bfloat16 v = bsel ? __float2bfloat16(w - __bfloat162float(hi)) : hi;
        out |= (uint32_t)__bfloat16_as_ushort(v) << (s * 16);
    }
    dst[idx] = out;
}

// Inject x_t at channel 128 (hi/lo) of act0[t&1].
__global__ void inject_x(const float* __restrict__ hist, int t, __nv_bfloat16* __restrict__ act) {
    int idx = blockIdx.x * blockDim.x + threadIdx.x;
    if (idx >= NB * 4096) return;
    int b = idx >> 12, px = idx & 4095;
    float v = hist[((size_t)b * LT + t) * 4096 + px];
    size_t e = (((size_t)b * PADW + (px >> 6) + 1) * PADW + ((px & 63) + 1)) * CH + 128;
    __nv_bfloat16 hi = __float2bfloat16(v);
    act[e] = hi;
    act[PLANE + e] = __float2bfloat16(v - __bfloat162float(hi));
}

// ==================== fused ConvLSTM step: implicit GEMM on mma.sync bf16 ====================
// CTA: M=256 px (4 image rows), N=64 gate-interleaved oc'. 8 warps = 4(M) x 2(N), warp 64x32.
// K loop: pass(A hi/lo) x 9 k-chunks x 9 taps x (B hi[,lo]).
__global__ void __launch_bounds__(256, 2)
step_mma(const __nv_bfloat16* __restrict__ act,      // hi plane; lo = act + PLANE
         const uint32_t* __restrict__ fragB, int ntiles,
         const float* __restrict__ bias, int HIDT,
         float* __restrict__ cstate,
         __nv_bfloat16* hdst_a, __nv_bfloat16* hdst_b, int ch_off,
         float* out_final) {
    extern __shared__ unsigned char smem[];
    __nv_bfloat16* sA = (__nv_bfloat16*)smem;                 // 396 rows x 48B (24 elems)
    uint32_t* sB = (uint32_t*)(smem + 19456);                 // 9216 u32 = 36864B
    const uint32_t sAsh = (uint32_t)__cvta_generic_to_shared(sA);
    const uint32_t sBsh = sAsh + 19456;

    const int tid = threadIdx.x, lane = tid & 31, warp = tid >> 5;
    const int warpM = warp & 3, warpN = warp >> 2;
    const int R4 = blockIdx.x * 4;           // image-row base (also padded slab row base)
    const int b  = blockIdx.y;
    const int zt = blockIdx.z;
    const int nro = zt * 64;

    float acc[4][4][4];
#pragma unroll
    for (int m = 0; m < 4; ++m)
#pragma unroll
        for (int i = 0; i < 4; ++i)
#pragma unroll
            for (int k = 0; k < 4; ++k) acc[m][i][k] = 0.f;

    const size_t actbase = ((size_t)b * PADW + R4) * PADW * CH;

    for (int pass = 0; pass < 2; ++pass) {
        const __nv_bfloat16* pl = act + (pass ? PLANE : 0);
        const int nb = pass ? 1 : 2;
        for (int kc = 0; kc < 9; ++kc) {
            __syncthreads();    // previous phase compute done before overwriting smem
            // A slab: 396 rows (6 padded rows x 66 px), 16 ch each, row stride 48B
            for (int i = tid; i < 396 * 2; i += 256) {
                int rowid = i >> 1, half = i & 1;
                cpa16(sAsh + rowid * 48 + half * 16,
                      pl + actbase + (size_t)rowid * CH + kc * 16 + half * 8);
            }
            // B block for this (kc, ztile): [tap][bsel][nsub][lane][reg]; skip bsel=1 on pass1
            {
                const uint4* src = (const uint4*)fragB + (size_t)(kc * ntiles + zt) * 2304;
                for (int i = tid; i < 2304; i += 256) {
                    if (pass == 1 && ((i >> 7) & 1)) continue;   // 128 uint4 per (tap,bsel)
                    cpa16(sBsh + i * 16, src + i);
                }
            }
            cpa_commit_wait();
            __syncthreads();
#pragma unroll
            for (int tap = 0; tap < 9; ++tap) {
                const int ky = tap / 3, kx = tap % 3;
                uint32_t a[4][4];
#pragma unroll
                for (int msub = 0; msub < 4; ++msub) {
                    int m = warpM * 64 + msub * 16 + (lane & 15);
                    int srow = ((m >> 6) + ky) * 66 + (m & 63) + kx;
                    uint32_t ad = sAsh + srow * 48 + (lane >> 4) * 16;
                    asm volatile("ldmatrix.sync.aligned.m8n8.x4.shared.b16 {%0,%1,%2,%3}, [%4];"
                        : "=r"(a[msub][0]), "=r"(a[msub][1]), "=r"(a[msub][2]), "=r"(a[msub][3])
                        : "r"(ad));
                }
                for (int bsel = 0; bsel < nb; ++bsel) {
#pragma unroll
                    for (int i = 0; i < 4; ++i) {
                        const uint32_t* bp = sB + ((((tap * 2 + bsel) * 8) + warpN * 4 + i) * 32 + lane) * 2;
                        uint32_t b0 = bp[0], b1 = bp[1];
#pragma unroll
                        for (int msub = 0; msub < 4; ++msub) {
                            asm volatile(
                                "mma.sync.aligned.m16n8k16.row.col.f32.bf16.bf16.f32 "
                                "{%0,%1,%2,%3}, {%4,%5,%6,%7}, {%8,%9}, {%0,%1,%2,%3};"
                                : "+f"(acc[msub][i][0]), "+f"(acc[msub][i][1]),
                                  "+f"(acc[msub][i][2]), "+f"(acc[msub][i][3])
                                : "r"(a[msub][0]), "r"(a[msub][1]), "r"(a[msub][2]), "r"(a[msub][3]),
                                  "r"(b0), "r"(b1));
                        }
                    }
                }
            }
        }
    }

    // ---- epilogue: gather 4 gates per (px,hid) via shfl, LSTM update ----
    const int q = lane & 3;
    const bool evenq = !(q & 1);
#pragma unroll
    for (int msub = 0; msub < 4; ++msub) {
#pragma unroll
        for (int i = 0; i < 4; ++i) {
            float d0 = acc[msub][i][0], d1 = acc[msub][i][1];
            float d2 = acc[msub][i][2], d3 = acc[msub][i][3];
            float s0 = evenq ? d2 : d0;
            float s1 = evenq ? d3 : d1;
            float t0 = __shfl_xor_sync(0xffffffffu, s0, 1);
            float t1 = __shfl_xor_sync(0xffffffffu, s1, 1);
            float zi, zf, zo, zg;
            int pr;
            if (evenq) { zi = d0; zf = d1; zo = t0; zg = t1; pr = lane >> 2; }
            else       { zi = t0; zf = t1; zo = d2; zg = d3; pr = (lane >> 2) + 8; }
            const int m = warpM * 64 + msub * 16 + pr;
            const int hid = (nro >> 2) + warpN * 8 + i * 2 + (q >> 1);
            if (hid < HIDT) {
                zi += bias[hid];
                zf += bias[HIDT + hid];
                zo += bias[2 * HIDT + hid];
                zg += bias[3 * HIDT + hid];
                const int r_im = m >> 6, x = m & 63;
                const size_t cidx = ((size_t)b * 4096 + (R4 + r_im) * 64 + x) * HIDT + hid;
                float cp = cstate[cidx];
                float cn = fsig(zf) * cp + fsig(zi) * ftanh(zg);
                float hn = fsig(zo) * ftanh(cn);
                cstate[cidx] = cn;
                __nv_bfloat16 hi = __float2bfloat16(hn);
                __nv_bfloat16 lo = __float2bfloat16(hn - __bfloat162float(hi));
                const size_t e = (((size_t)b * PADW + R4 + r_im + 1) * PADW + x + 1) * CH + ch_off + hid;
                if (hdst_a) { hdst_a[e] = hi; hdst_a[PLANE + e] = lo; }
                if (hdst_b) { hdst_b[e] = hi; hdst_b[PLANE + e] = lo; }
                if (out_final)
                    out_final[((size_t)b * HIDT + hid) * 4096 + (R4 + r_im) * 64 + x] = hn;
            }
        }
    }
}

// ==================== host ====================
extern "C" void kernel_launch(void* const* d_in, const int* in_sizes, int n_in,
                              void* d_out, int out_size) {
    const float* hist = (const float*)d_in[0];
    const float* W0   = (const float*)d_in[2];
    const float* b0   = (const float*)d_in[3];
    const float* W1   = (const float*)d_in[4];
    const float* b1   = (const float*)d_in[5];
    float* out = (float*)d_out;

    __nv_bfloat16 *a0p, *a1p;
    float *c0p, *c1p;
    uint32_t *fb0, *fb1;
    cudaGetSymbolAddress((void**)&a0p, g_act0);
    cudaGetSymbolAddress((void**)&a1p, g_act1);
    cudaGetSymbolAddress((void**)&c0p, g_c0);
    cudaGetSymbolAddress((void**)&c1p, g_c1);
    cudaGetSymbolAddress((void**)&fb0, g_fb0);
    cudaGetSymbolAddress((void**)&fb1, g_fb1);

    const int SMEM = 19456 + 36864;   // 56320
    cudaFuncSetAttribute(step_mma, cudaFuncAttributeMaxDynamicSharedMemorySize, SMEM);

    // deterministic replay: zero state + activations
    fill16<<<2048, 256>>>((uint4*)a0p, 4 * PLANE / 8);
    fill16<<<2048, 256>>>((uint4*)a1p, 4 * PLANE / 8);
    fill16<<<2048, 256>>>((uint4*)c0p, (size_t)NB * 4096 * 128 / 4);
    fill16<<<512,  256>>>((uint4*)c1p, (size_t)NB * 4096 * 12 / 4);

    const int tot0 = 9 * 8 * 9 * 2 * 8 * 32 * 2;
    const int tot1 = 9 * 1 * 9 * 2 * 8 * 32 * 2;
    prep_w<<<(tot0 + 255) / 256, 256>>>(W0, fb0, 128, 8, 129, 1, tot0);
    prep_w<<<(tot1 + 255) / 256, 256>>>(W1, fb1, 12, 1, 140, 0, tot1);

    const size_t BUF = 2 * PLANE;
    for (int t = 0; t < LT; ++t) {
        __nv_bfloat16* act0_t = a0p + (size_t)(t & 1) * BUF;
        __nv_bfloat16* act0_n = a0p + (size_t)((t + 1) & 1) * BUF;
        __nv_bfloat16* act1_t = a1p + (size_t)(t & 1) * BUF;
        __nv_bfloat16* act1_n = a1p + (size_t)((t + 1) & 1) * BUF;

        inject_x<<<256, 256>>>(hist, t, act0_t);
        // L0: reads act0[t]; writes h0 -> act0[t+1] ch0..127 and act1[t] ch0..127
        step_mma<<<dim3(16, 16, 8), 256, SMEM>>>(
            act0_t, fb0, 8, b0, 128, c0p, act0_n, act1_t, 0, nullptr);
        // L1: reads act1[t]; writes h1 -> act1[t+1] ch128..139; last step -> out
        step_mma<<<dim3(16, 16, 1), 256, SMEM>>>(
            act1_t, fb1, 1, b1, 12, c1p,
            (t < LT - 1) ? act1_n : nullptr, nullptr, 128,
            (t == LT - 1) ? out : nullptr);
    }
}